// round 3
// baseline (speedup 1.0000x reference)
#include <cuda_runtime.h>
#include <math.h>

#define BB 8
#define NNODE 512
#define TT 64
#define NINP 64
#define NE 128
#define NH 128
#define RTOT (BB*NNODE)     /* 4096 */
#define G4 (4*NH)           /* 512  */
#define UVW (NE + G4)       /* 640  */
#define KC 16

typedef unsigned long long ull;

// ---------------- scratch (allocation-free: __device__ globals) ----------------
__device__ float g_An[BB*NNODE*NNODE];   // 8.4 MB  normalized adjacency
__device__ float g_dinv[RTOT];
__device__ float g_c[RTOT*NH];
__device__ float g_u0[RTOT*NE];          // ping-pong u = h @ Wpe
__device__ float g_u1[RTOT*NE];
__device__ float g_hw[RTOT*G4];          // h @ [Whi|Whf|Whg|Who]  (row-local)
__device__ float g_es[RTOT*NE];
__device__ float g_esW[RTOT*G4];         // step-invariant gate preactivation
__device__ float g_Xi[RTOT*NINP];
__device__ float g_Wcomb[NE*UVW];        // [Wpe | Whi|Whf|Whg|Who]
__device__ float g_WgH[NE*G4];           // bottom halves of Wii|Wif|Wig|Wio
__device__ float g_Wtop[NE*G4];          // top halves
__device__ float g_cvec[G4];             // b + bh + bpe@W_bot

__device__ __forceinline__ float sigm(float x) { return 1.f / (1.f + __expf(-x)); }

// ---------------- packed f32x2 helpers (sm_103a FFMA2 path) ----------------
__device__ __forceinline__ ull dup2(float x) {
    ull r; asm("mov.b64 %0, {%1,%1};" : "=l"(r) : "f"(x)); return r;
}
__device__ __forceinline__ void fma2(ull &d, ull a, ull b) {
    asm("fma.rn.f32x2 %0, %1, %2, %0;" : "+l"(d) : "l"(a), "l"(b));
}
__device__ __forceinline__ ull add2(ull a, ull b) {
    ull r; asm("add.rn.f32x2 %0, %1, %2;" : "=l"(r) : "l"(a), "l"(b)); return r;
}
__device__ __forceinline__ float2 unpk(ull v) {
    float2 f; asm("mov.b64 {%0,%1}, %2;" : "=f"(f.x), "=f"(f.y) : "l"(v)); return f;
}

// ---------------- prep kernels ----------------
__global__ void prep_weights(
    const float* __restrict__ Wpe, const float* __restrict__ bpe,
    const float* __restrict__ Wii, const float* __restrict__ bii,
    const float* __restrict__ Whi, const float* __restrict__ bhi,
    const float* __restrict__ Wif, const float* __restrict__ bif_,
    const float* __restrict__ Whf, const float* __restrict__ bhf,
    const float* __restrict__ Wig, const float* __restrict__ big_,
    const float* __restrict__ Whg, const float* __restrict__ bhg,
    const float* __restrict__ Wio, const float* __restrict__ bio,
    const float* __restrict__ Who, const float* __restrict__ bho)
{
    int idx = blockIdx.x * blockDim.x + threadIdx.x;
    const float* Wg[4]  = {Wii, Wif, Wig, Wio};
    const float* Whx[4] = {Whi, Whf, Whg, Who};
    const float* bg[4]  = {bii, bif_, big_, bio};
    const float* bhx[4] = {bhi, bhf, bhg, bho};

    if (idx < NE*UVW) {                       // Wcomb
        int k = idx / UVW, j = idx % UVW;
        float v;
        if (j < NE) v = Wpe[k*NE + j];
        else { int j2 = j - NE; int g = j2 >> 7, o = j2 & 127; v = Whx[g][k*NH + o]; }
        g_Wcomb[idx] = v;
    }
    int i2 = idx - NE*UVW;
    if (i2 >= 0 && i2 < NE*G4) {              // WgH + Wtop
        int k = i2 / G4, go = i2 % G4; int g = go >> 7, o = go & 127;
        g_WgH[i2]  = Wg[g][(NE + k)*NH + o];
        g_Wtop[i2] = Wg[g][k*NH + o];
    }
    int i3 = i2 - NE*G4;
    if (i3 >= 0 && i3 < G4) {                 // cvec
        int g = i3 >> 7, o = i3 & 127;
        float s = bg[g][o] + bhx[g][o];
        for (int k = 0; k < NE; k++) s += bpe[k] * Wg[g][(NE + k)*NH + o];
        g_cvec[i3] = s;
    }
}

__global__ void prep_dinv(const float* __restrict__ A)
{
    int row = blockIdx.x;                     // b*512 + i
    const float* Ar = A + (size_t)row * NNODE;
    float s = 0.f;
    for (int j = threadIdx.x; j < NNODE; j += blockDim.x) s += Ar[j];
    __shared__ float red[4];
    for (int o = 16; o > 0; o >>= 1) s += __shfl_down_sync(0xffffffff, s, o);
    if ((threadIdx.x & 31) == 0) red[threadIdx.x >> 5] = s;
    __syncthreads();
    if (threadIdx.x == 0) {
        float d = red[0] + red[1] + red[2] + red[3];
        g_dinv[row] = d > 0.f ? rsqrtf(d) : 0.f;
    }
}

__global__ void prep_An(const float* __restrict__ A)
{
    int idx = blockIdx.x * blockDim.x + threadIdx.x;
    if (idx >= BB*NNODE*NNODE) return;
    int j  = idx & (NNODE - 1);
    int bi = idx >> 9;                        // b*512 + i
    int b  = idx >> 18;
    g_An[idx] = A[idx] * g_dinv[bi] * g_dinv[(b << 9) + j];
}

__global__ void prep_init(const float* __restrict__ X, float* __restrict__ out)
{
    int idx = blockIdx.x * blockDim.x + threadIdx.x;
    if (idx < RTOT*NH) { g_u0[idx] = 0.f; g_c[idx] = 0.f; }
    if (idx < RTOT*G4) g_hw[idx] = 0.f;
    if (idx < RTOT*NINP) {
        int r = idx >> 6, c = idx & 63;
        float v = X[(size_t)r * (TT*NINP) + c];   // X[b,n,0,c]
        g_Xi[idx] = v;
        out[(size_t)r * (TT*NINP) + c] = v;       // t = 0 slice
    }
}

__global__ void prep_es(const float* __restrict__ X,
                        const float* __restrict__ Wse, const float* __restrict__ bse)
{
    int r = blockIdx.x;
    __shared__ float xs[NINP];
    if (threadIdx.x < NINP) xs[threadIdx.x] = X[(size_t)r * (TT*NINP) + threadIdx.x];
    __syncthreads();
    int j = threadIdx.x;
    float s = bse[j];
    #pragma unroll 8
    for (int k = 0; k < NINP; k++) s += xs[k] * Wse[k*NE + j];
    g_es[r*NE + j] = s;
}

// ------------- generic SGEMM (used once for esW) -------------
__global__ __launch_bounds__(256) void sgemm_t32(
    const float* __restrict__ A, int lda,
    const float* __restrict__ B, int ldb,
    float* __restrict__ C, int ldc,
    int K, const float* __restrict__ bias)
{
    const float* Ab = A + (size_t)blockIdx.x * 32 * lda;
    const float* Bb = B + (size_t)blockIdx.y * 128;
    float*       Cb = C + (size_t)blockIdx.x * 32 * ldc + (size_t)blockIdx.y * 128;

    __shared__ float AsT[KC][36];
    __shared__ float Bss[KC][128];

    int tid = threadIdx.x;
    int tx = tid & 31, ty = tid >> 5;
    int r0 = ty * 4, c0 = tx * 4;

    float acc[4][4];
    #pragma unroll
    for (int i = 0; i < 4; i++)
        #pragma unroll
        for (int j = 0; j < 4; j++) acc[i][j] = 0.f;

    for (int kk = 0; kk < K; kk += KC) {
        #pragma unroll
        for (int e = 0; e < 2; e++) {
            int el = 2*tid + e;
            int ar = el >> 4, ak = el & 15;
            AsT[ak][ar] = Ab[(size_t)ar * lda + kk + ak];
        }
        #pragma unroll
        for (int e = 0; e < 8; e++) {
            int el = tid + e * 256;
            int bk = el >> 7, bc = el & 127;
            Bss[bk][bc] = Bb[(size_t)(kk + bk) * ldb + bc];
        }
        __syncthreads();
        #pragma unroll
        for (int k = 0; k < KC; k++) {
            float4 av = *(const float4*)&AsT[k][r0];
            float4 bv = *(const float4*)&Bss[k][c0];
            float a[4] = {av.x, av.y, av.z, av.w};
            float b[4] = {bv.x, bv.y, bv.z, bv.w};
            #pragma unroll
            for (int i = 0; i < 4; i++)
                #pragma unroll
                for (int j = 0; j < 4; j++) acc[i][j] += a[i] * b[j];
        }
        __syncthreads();
    }
    #pragma unroll
    for (int i = 0; i < 4; i++) {
        float4 v = make_float4(acc[i][0], acc[i][1], acc[i][2], acc[i][3]);
        if (bias) {
            const float4 bv = *(const float4*)&bias[blockIdx.y*128 + c0];
            v.x += bv.x; v.y += bv.y; v.z += bv.z; v.w += bv.w;
        }
        *(float4*)&Cb[(size_t)(r0 + i) * ldc + c0] = v;
    }
}

// ------------- fused per-step kernel -------------
// 128 blocks x 256 threads; block owns rows rg..rg+31.
// Phase 1: Hu = An @ u_in   (K=512)          -> smem HuT
// Phase 2: gates = esW + hw + Hu@WgH; LSTM state update (c in global, rest regs)
// Phase 3: u_out = h_t@Wpe ; g_hw = h_t@Wh*  (next step's inputs)
// Phase 4: Xi += h_t@Wout + bout; write output slice t
__global__ __launch_bounds__(256) void step_kernel(
    const float* __restrict__ u_in, float* __restrict__ u_out,
    float* __restrict__ out, const float* __restrict__ Wout,
    const float* __restrict__ bout, int t)
{
    __shared__ float AsT[32][34];
    __shared__ float HuT[128][34];
    __shared__ float Bs[32][128];

    const int tid = threadIdx.x;
    const int cx = tid & 15, ry = tid >> 4;
    const int c0 = cx * 8, r0 = ry * 2;
    const int rg = blockIdx.x * 32;
    const int bbase = (rg >> 9) << 9;          // first row of this batch

    // ---------------- Phase 1: Hu = An @ u_in ----------------
    ull acc[2][4];
    #pragma unroll
    for (int r = 0; r < 2; r++)
        #pragma unroll
        for (int j = 0; j < 4; j++) acc[r][j] = 0ULL;

    for (int kk = 0; kk < NNODE; kk += 32) {
        {   // An chunk: 32 rows x 32 k
            int row = tid >> 3, k0 = (tid & 7) * 4;
            float4 v = *(const float4*)&g_An[(size_t)(rg + row) * NNODE + kk + k0];
            AsT[k0+0][row] = v.x; AsT[k0+1][row] = v.y;
            AsT[k0+2][row] = v.z; AsT[k0+3][row] = v.w;
        }
        {   // u chunk: 32 k x 128
            int kr = tid >> 5, c = (tid * 4) & 127;
            #pragma unroll
            for (int e = 0; e < 4; e++)
                *(float4*)&Bs[kr + e*8][c] =
                    *(const float4*)&u_in[(size_t)(bbase + kk + kr + e*8) * NE + c];
        }
        __syncthreads();
        #pragma unroll
        for (int k = 0; k < 32; k++) {
            float2 av = *(const float2*)&AsT[k][r0];
            ull a0 = dup2(av.x), a1 = dup2(av.y);
            ulonglong2 b01 = *(const ulonglong2*)&Bs[k][c0];
            ulonglong2 b23 = *(const ulonglong2*)&Bs[k][c0 + 4];
            fma2(acc[0][0], a0, b01.x); fma2(acc[0][1], a0, b01.y);
            fma2(acc[0][2], a0, b23.x); fma2(acc[0][3], a0, b23.y);
            fma2(acc[1][0], a1, b01.x); fma2(acc[1][1], a1, b01.y);
            fma2(acc[1][2], a1, b23.x); fma2(acc[1][3], a1, b23.y);
        }
        __syncthreads();
    }
    #pragma unroll
    for (int r = 0; r < 2; r++)
        #pragma unroll
        for (int j = 0; j < 4; j++) {
            float2 p = unpk(acc[r][j]);
            HuT[c0 + 2*j    ][r0 + r] = p.x;
            HuT[c0 + 2*j + 1][r0 + r] = p.y;
        }
    __syncthreads();

    // ---------------- Phase 2: gates ----------------
    float rb[2][8], hval[2][8];
    const int order[4] = {0, 2, 1, 3};          // i, g, f, o

    #pragma unroll
    for (int p = 0; p < 4; p++) {
        const int gb = order[p] << 7;
        ull ga[2][4];
        #pragma unroll
        for (int r = 0; r < 2; r++) {
            size_t base = (size_t)(rg + r0 + r) * G4 + gb + c0;
            ulonglong2 e01 = *(const ulonglong2*)&g_esW[base];
            ulonglong2 e23 = *(const ulonglong2*)&g_esW[base + 4];
            ulonglong2 h01 = *(const ulonglong2*)&g_hw[base];
            ulonglong2 h23 = *(const ulonglong2*)&g_hw[base + 4];
            ga[r][0] = add2(e01.x, h01.x); ga[r][1] = add2(e01.y, h01.y);
            ga[r][2] = add2(e23.x, h23.x); ga[r][3] = add2(e23.y, h23.y);
        }
        for (int kk = 0; kk < NH; kk += 32) {
            int kr = tid >> 5, c = (tid * 4) & 127;
            #pragma unroll
            for (int e = 0; e < 4; e++)
                *(float4*)&Bs[kr + e*8][c] =
                    *(const float4*)&g_WgH[(size_t)(kk + kr + e*8) * G4 + gb + c];
            __syncthreads();
            #pragma unroll
            for (int k = 0; k < 32; k++) {
                float2 av = *(const float2*)&HuT[kk + k][r0];
                ull a0 = dup2(av.x), a1 = dup2(av.y);
                ulonglong2 b01 = *(const ulonglong2*)&Bs[k][c0];
                ulonglong2 b23 = *(const ulonglong2*)&Bs[k][c0 + 4];
                fma2(ga[0][0], a0, b01.x); fma2(ga[0][1], a0, b01.y);
                fma2(ga[0][2], a0, b23.x); fma2(ga[0][3], a0, b23.y);
                fma2(ga[1][0], a1, b01.x); fma2(ga[1][1], a1, b01.y);
                fma2(ga[1][2], a1, b23.x); fma2(ga[1][3], a1, b23.y);
            }
            __syncthreads();
        }
        float gv[2][8];
        #pragma unroll
        for (int r = 0; r < 2; r++)
            #pragma unroll
            for (int j = 0; j < 4; j++) {
                float2 q = unpk(ga[r][j]);
                gv[r][2*j] = q.x; gv[r][2*j + 1] = q.y;
            }
        if (p == 0) {                           // i
            #pragma unroll
            for (int r = 0; r < 2; r++)
                #pragma unroll
                for (int j = 0; j < 8; j++) rb[r][j] = sigm(gv[r][j]);
        } else if (p == 1) {                    // g
            #pragma unroll
            for (int r = 0; r < 2; r++)
                #pragma unroll
                for (int j = 0; j < 8; j++) rb[r][j] *= tanhf(gv[r][j]);
        } else if (p == 2) {                    // f : c update
            #pragma unroll
            for (int r = 0; r < 2; r++) {
                size_t cb = (size_t)(rg + r0 + r) * NH + c0;
                float4 ca = *(const float4*)&g_c[cb];
                float4 cbb = *(const float4*)&g_c[cb + 4];
                float cold[8] = {ca.x, ca.y, ca.z, ca.w, cbb.x, cbb.y, cbb.z, cbb.w};
                float cn[8];
                #pragma unroll
                for (int j = 0; j < 8; j++) {
                    cn[j] = sigm(gv[r][j]) * cold[j] + rb[r][j];
                    rb[r][j] = tanhf(cn[j]);
                }
                *(float4*)&g_c[cb]     = make_float4(cn[0], cn[1], cn[2], cn[3]);
                *(float4*)&g_c[cb + 4] = make_float4(cn[4], cn[5], cn[6], cn[7]);
            }
        } else {                                // o
            #pragma unroll
            for (int r = 0; r < 2; r++)
                #pragma unroll
                for (int j = 0; j < 8; j++) hval[r][j] = sigm(gv[r][j]) * rb[r][j];
        }
    }

    // h_t into HuT (transposed), replacing Hu
    __syncthreads();
    #pragma unroll
    for (int r = 0; r < 2; r++)
        #pragma unroll
        for (int j = 0; j < 8; j++) HuT[c0 + j][r0 + r] = hval[r][j];
    __syncthreads();

    // ---------------- Phase 3: u_out = h@Wpe, g_hw = h@Wh* ----------------
    #pragma unroll 1
    for (int nb = 0; nb < UVW; nb += 128) {
        ull a3[2][4];
        #pragma unroll
        for (int r = 0; r < 2; r++)
            #pragma unroll
            for (int j = 0; j < 4; j++) a3[r][j] = 0ULL;
        for (int kk = 0; kk < NH; kk += 32) {
            int kr = tid >> 5, c = (tid * 4) & 127;
            #pragma unroll
            for (int e = 0; e < 4; e++)
                *(float4*)&Bs[kr + e*8][c] =
                    *(const float4*)&g_Wcomb[(size_t)(kk + kr + e*8) * UVW + nb + c];
            __syncthreads();
            #pragma unroll
            for (int k = 0; k < 32; k++) {
                float2 av = *(const float2*)&HuT[kk + k][r0];
                ull a0 = dup2(av.x), a1 = dup2(av.y);
                ulonglong2 b01 = *(const ulonglong2*)&Bs[k][c0];
                ulonglong2 b23 = *(const ulonglong2*)&Bs[k][c0 + 4];
                fma2(a3[0][0], a0, b01.x); fma2(a3[0][1], a0, b01.y);
                fma2(a3[0][2], a0, b23.x); fma2(a3[0][3], a0, b23.y);
                fma2(a3[1][0], a1, b01.x); fma2(a3[1][1], a1, b01.y);
                fma2(a3[1][2], a1, b23.x); fma2(a3[1][3], a1, b23.y);
            }
            __syncthreads();
        }
        #pragma unroll
        for (int r = 0; r < 2; r++) {
            float2 q0 = unpk(a3[r][0]), q1 = unpk(a3[r][1]);
            float2 q2 = unpk(a3[r][2]), q3 = unpk(a3[r][3]);
            float4 v0 = make_float4(q0.x, q0.y, q1.x, q1.y);
            float4 v1 = make_float4(q2.x, q2.y, q3.x, q3.y);
            size_t row = rg + r0 + r;
            if (nb == 0) {
                *(float4*)&u_out[row * NE + c0]     = v0;
                *(float4*)&u_out[row * NE + c0 + 4] = v1;
            } else {
                *(float4*)&g_hw[row * G4 + (nb - 128) + c0]     = v0;
                *(float4*)&g_hw[row * G4 + (nb - 128) + c0 + 4] = v1;
            }
        }
    }

    // ---------------- Phase 4: out = Xi + h@Wout + bout ----------------
    const int c4 = cx * 4;
    ull a4[2][2];
    #pragma unroll
    for (int r = 0; r < 2; r++) {
        ulonglong2 xi = *(const ulonglong2*)&g_Xi[(size_t)(rg + r0 + r) * NINP + c4];
        ulonglong2 bo = *(const ulonglong2*)&bout[c4];
        a4[r][0] = add2(xi.x, bo.x);
        a4[r][1] = add2(xi.y, bo.y);
    }
    for (int kk = 0; kk < NH; kk += 32) {
        int kr = tid >> 4, c = (tid * 4) & 63;
        #pragma unroll
        for (int e = 0; e < 2; e++)
            *(float4*)&Bs[kr + e*16][c] =
                *(const float4*)&Wout[(size_t)(kk + kr + e*16) * NINP + c];
        __syncthreads();
        #pragma unroll
        for (int k = 0; k < 32; k++) {
            float2 av = *(const float2*)&HuT[kk + k][r0];
            ull a0 = dup2(av.x), a1 = dup2(av.y);
            ulonglong2 b = *(const ulonglong2*)&Bs[k][c4];
            fma2(a4[0][0], a0, b.x); fma2(a4[0][1], a0, b.y);
            fma2(a4[1][0], a1, b.x); fma2(a4[1][1], a1, b.y);
        }
        __syncthreads();
    }
    #pragma unroll
    for (int r = 0; r < 2; r++) {
        float2 q0 = unpk(a4[r][0]), q1 = unpk(a4[r][1]);
        float4 v = make_float4(q0.x, q0.y, q1.x, q1.y);
        size_t row = rg + r0 + r;
        *(float4*)&g_Xi[row * NINP + c4] = v;
        *(float4*)&out[row * (TT*NINP) + (size_t)t * NINP + c4] = v;
    }
}

// ---------------- launch ----------------
extern "C" void kernel_launch(void* const* d_in, const int* in_sizes, int n_in,
                              void* d_out, int out_size)
{
    const float* X    = (const float*)d_in[0];
    const float* A    = (const float*)d_in[1];
    const float* Wse  = (const float*)d_in[2];
    const float* bse  = (const float*)d_in[3];
    const float* Wpe  = (const float*)d_in[4];
    const float* bpe  = (const float*)d_in[5];
    const float* Wii  = (const float*)d_in[6];
    const float* bii  = (const float*)d_in[7];
    const float* Whi  = (const float*)d_in[8];
    const float* bhi  = (const float*)d_in[9];
    const float* Wif  = (const float*)d_in[10];
    const float* bif_ = (const float*)d_in[11];
    const float* Whf  = (const float*)d_in[12];
    const float* bhf  = (const float*)d_in[13];
    const float* Wig  = (const float*)d_in[14];
    const float* big_ = (const float*)d_in[15];
    const float* Whg  = (const float*)d_in[16];
    const float* bhg  = (const float*)d_in[17];
    const float* Wio  = (const float*)d_in[18];
    const float* bio  = (const float*)d_in[19];
    const float* Who  = (const float*)d_in[20];
    const float* bho  = (const float*)d_in[21];
    const float* Wout = (const float*)d_in[22];
    const float* bout = (const float*)d_in[23];
    float* out = (float*)d_out;

    float *p_es, *p_esW, *p_u0, *p_u1, *p_Wtop, *p_cvec;
    cudaGetSymbolAddress((void**)&p_es,   g_es);
    cudaGetSymbolAddress((void**)&p_esW,  g_esW);
    cudaGetSymbolAddress((void**)&p_u0,   g_u0);
    cudaGetSymbolAddress((void**)&p_u1,   g_u1);
    cudaGetSymbolAddress((void**)&p_Wtop, g_Wtop);
    cudaGetSymbolAddress((void**)&p_cvec, g_cvec);

    prep_weights<<<(NE*UVW + NE*G4 + G4 + 255)/256, 256>>>(
        Wpe, bpe, Wii, bii, Whi, bhi, Wif, bif_, Whf, bhf,
        Wig, big_, Whg, bhg, Wio, bio, Who, bho);
    prep_dinv<<<RTOT, 128>>>(A);
    prep_An<<<(BB*NNODE*NNODE + 255)/256, 256>>>(A);
    prep_init<<<(RTOT*G4 + 255)/256, 256>>>(X, out);
    prep_es<<<RTOT, 128>>>(X, Wse, bse);

    // esW = es @ Wtop + cvec      (M=4096, K=128, N=512)
    sgemm_t32<<<dim3(RTOT/32, G4/128), 256>>>(
        p_es, NE, p_Wtop, G4, p_esW, G4, NE, p_cvec);

    for (int t = 1; t < TT; ++t) {
        float* u_in  = (t & 1) ? p_u0 : p_u1;
        float* u_out = (t & 1) ? p_u1 : p_u0;
        step_kernel<<<RTOT/32, 256>>>(u_in, u_out, out, Wout, bout, t);
    }
}

// round 4
// speedup vs baseline: 1.1099x; 1.1099x over previous
#include <cuda_runtime.h>
#include <math.h>

#define BB 8
#define NNODE 512
#define TT 64
#define NINP 64
#define NE 128
#define NH 128
#define RTOT (BB*NNODE)     /* 4096 */
#define G4 (4*NH)           /* 512  */
#define UVW (NE + G4)       /* 640  */

// ---------------- scratch (allocation-free: __device__ globals) ----------------
__device__ float g_An_h[BB*NNODE*NNODE];
__device__ float g_An_l[BB*NNODE*NNODE];
__device__ float g_dinv[RTOT];
__device__ float g_c[RTOT*NH];
__device__ float g_u_h[RTOT*NE];
__device__ float g_u_l[RTOT*NE];
__device__ float g_h_h[RTOT*NE];
__device__ float g_h_l[RTOT*NE];
__device__ float g_Hu_h[RTOT*NE];
__device__ float g_Hu_l[RTOT*NE];
__device__ float g_hw[RTOT*G4];
__device__ float g_es[RTOT*NE];
__device__ float g_esW[RTOT*G4];
__device__ float g_Xi[RTOT*NINP];
__device__ float g_Wc_h[NE*UVW];
__device__ float g_Wc_l[NE*UVW];
__device__ float g_Wg_h[NE*G4];
__device__ float g_Wg_l[NE*G4];
__device__ float g_Wo_h[NH*NINP];
__device__ float g_Wo_l[NH*NINP];
__device__ float g_Wtop[NE*G4];
__device__ float g_cvec[G4];

__device__ __forceinline__ float sigm(float x) { return 1.f / (1.f + __expf(-x)); }

// ---------------- tf32 helpers ----------------
__device__ __forceinline__ unsigned f2tf(float x) {
    unsigned r; asm("cvt.rna.tf32.f32 %0, %1;" : "=r"(r) : "f"(x)); return r;
}
__device__ __forceinline__ void tfsplit(float x, float& hi, float& lo) {
    hi = __uint_as_float(f2tf(x));
    lo = __uint_as_float(f2tf(x - hi));
}
__device__ __forceinline__ void mma8(float4& c, const unsigned a[4], const unsigned b[2]) {
    asm("mma.sync.aligned.m16n8k8.row.col.f32.tf32.tf32.f32 "
        "{%0,%1,%2,%3}, {%4,%5,%6,%7}, {%8,%9}, {%0,%1,%2,%3};"
        : "+f"(c.x), "+f"(c.y), "+f"(c.z), "+f"(c.w)
        : "r"(a[0]), "r"(a[1]), "r"(a[2]), "r"(a[3]), "r"(b[0]), "r"(b[1]));
}

// ---------------- prep kernels ----------------
__global__ void prep_weights(
    const float* __restrict__ Wpe, const float* __restrict__ bpe,
    const float* __restrict__ Wii, const float* __restrict__ bii,
    const float* __restrict__ Whi, const float* __restrict__ bhi,
    const float* __restrict__ Wif, const float* __restrict__ bif_,
    const float* __restrict__ Whf, const float* __restrict__ bhf,
    const float* __restrict__ Wig, const float* __restrict__ big_,
    const float* __restrict__ Whg, const float* __restrict__ bhg,
    const float* __restrict__ Wio, const float* __restrict__ bio,
    const float* __restrict__ Who, const float* __restrict__ bho,
    const float* __restrict__ Wout)
{
    int idx = blockIdx.x * blockDim.x + threadIdx.x;
    const float* Wg[4]  = {Wii, Wif, Wig, Wio};
    const float* Whx[4] = {Whi, Whf, Whg, Who};
    const float* bg[4]  = {bii, bif_, big_, bio};
    const float* bhx[4] = {bhi, bhf, bhg, bho};

    if (idx < NE*UVW) {                       // Wcomb = [Wpe | Whi|Whf|Whg|Who]
        int k = idx / UVW, j = idx % UVW;
        float v;
        if (j < NE) v = Wpe[k*NE + j];
        else { int j2 = j - NE; int g = j2 >> 7, o = j2 & 127; v = Whx[g][k*NH + o]; }
        float hi, lo; tfsplit(v, hi, lo);
        g_Wc_h[idx] = hi; g_Wc_l[idx] = lo;
    }
    int i2 = idx - NE*UVW;
    if (i2 >= 0 && i2 < NE*G4) {              // WgH (split) + Wtop (raw)
        int k = i2 / G4, go = i2 % G4; int g = go >> 7, o = go & 127;
        float vb = Wg[g][(NE + k)*NH + o];
        float hi, lo; tfsplit(vb, hi, lo);
        g_Wg_h[i2] = hi; g_Wg_l[i2] = lo;
        g_Wtop[i2] = Wg[g][k*NH + o];
    }
    int i3 = i2 - NE*G4;
    if (i3 >= 0 && i3 < G4) {                 // cvec = b + bh + bpe@W_bot
        int g = i3 >> 7, o = i3 & 127;
        float s = bg[g][o] + bhx[g][o];
        for (int k = 0; k < NE; k++) s += bpe[k] * Wg[g][(NE + k)*NH + o];
        g_cvec[i3] = s;
    }
    int i4 = i3 - G4;
    if (i4 >= 0 && i4 < NH*NINP) {            // Wout split
        float hi, lo; tfsplit(Wout[i4], hi, lo);
        g_Wo_h[i4] = hi; g_Wo_l[i4] = lo;
    }
}

__global__ void prep_dinv(const float* __restrict__ A)
{
    int row = blockIdx.x;
    const float* Ar = A + (size_t)row * NNODE;
    float s = 0.f;
    for (int j = threadIdx.x; j < NNODE; j += blockDim.x) s += Ar[j];
    __shared__ float red[4];
    for (int o = 16; o > 0; o >>= 1) s += __shfl_down_sync(0xffffffff, s, o);
    if ((threadIdx.x & 31) == 0) red[threadIdx.x >> 5] = s;
    __syncthreads();
    if (threadIdx.x == 0) {
        float d = red[0] + red[1] + red[2] + red[3];
        g_dinv[row] = d > 0.f ? rsqrtf(d) : 0.f;
    }
}

__global__ void prep_An(const float* __restrict__ A)
{
    int idx = blockIdx.x * blockDim.x + threadIdx.x;
    if (idx >= BB*NNODE*NNODE) return;
    int j  = idx & (NNODE - 1);
    int bi = idx >> 9;
    int b  = idx >> 18;
    float v = A[idx] * g_dinv[bi] * g_dinv[(b << 9) + j];
    float hi, lo; tfsplit(v, hi, lo);
    g_An_h[idx] = hi; g_An_l[idx] = lo;
}

__global__ void prep_init(const float* __restrict__ X, float* __restrict__ out)
{
    int idx = blockIdx.x * blockDim.x + threadIdx.x;
    if (idx < RTOT*NH) { g_h_h[idx] = 0.f; g_h_l[idx] = 0.f; g_c[idx] = 0.f; }
    if (idx < RTOT*NINP) {
        int r = idx >> 6, c = idx & 63;
        float v = X[(size_t)r * (TT*NINP) + c];
        g_Xi[idx] = v;
        out[(size_t)r * (TT*NINP) + c] = v;
    }
}

__global__ void prep_es(const float* __restrict__ X,
                        const float* __restrict__ Wse, const float* __restrict__ bse)
{
    int r = blockIdx.x;
    __shared__ float xs[NINP];
    if (threadIdx.x < NINP) xs[threadIdx.x] = X[(size_t)r * (TT*NINP) + threadIdx.x];
    __syncthreads();
    int j = threadIdx.x;
    float s = bse[j];
    #pragma unroll 8
    for (int k = 0; k < NINP; k++) s += xs[k] * Wse[k*NE + j];
    g_es[r*NE + j] = s;
}

// ------------- scalar SGEMM (one-time, esW = es@Wtop + cvec) -------------
#define KC 16
__global__ __launch_bounds__(256) void sgemm_t32(
    const float* __restrict__ A, int lda,
    const float* __restrict__ B, int ldb,
    float* __restrict__ C, int ldc,
    int K, const float* __restrict__ bias)
{
    const float* Ab = A + (size_t)blockIdx.x * 32 * lda;
    const float* Bb = B + (size_t)blockIdx.y * 128;
    float*       Cb = C + (size_t)blockIdx.x * 32 * ldc + (size_t)blockIdx.y * 128;

    __shared__ float AsT[KC][36];
    __shared__ float Bss[KC][128];

    int tid = threadIdx.x;
    int tx = tid & 31, ty = tid >> 5;
    int r0 = ty * 4, c0 = tx * 4;

    float acc[4][4];
    #pragma unroll
    for (int i = 0; i < 4; i++)
        #pragma unroll
        for (int j = 0; j < 4; j++) acc[i][j] = 0.f;

    for (int kk = 0; kk < K; kk += KC) {
        #pragma unroll
        for (int e = 0; e < 2; e++) {
            int el = 2*tid + e;
            int ar = el >> 4, ak = el & 15;
            AsT[ak][ar] = Ab[(size_t)ar * lda + kk + ak];
        }
        #pragma unroll
        for (int e = 0; e < 8; e++) {
            int el = tid + e * 256;
            int bk = el >> 7, bc = el & 127;
            Bss[bk][bc] = Bb[(size_t)(kk + bk) * ldb + bc];
        }
        __syncthreads();
        #pragma unroll
        for (int k = 0; k < KC; k++) {
            float4 av = *(const float4*)&AsT[k][r0];
            float4 bv = *(const float4*)&Bss[k][c0];
            float a[4] = {av.x, av.y, av.z, av.w};
            float b[4] = {bv.x, bv.y, bv.z, bv.w};
            #pragma unroll
            for (int i = 0; i < 4; i++)
                #pragma unroll
                for (int j = 0; j < 4; j++) acc[i][j] += a[i] * b[j];
        }
        __syncthreads();
    }
    #pragma unroll
    for (int i = 0; i < 4; i++) {
        float4 v = make_float4(acc[i][0], acc[i][1], acc[i][2], acc[i][3]);
        if (bias) {
            const float4 bv = *(const float4*)&bias[blockIdx.y*128 + c0];
            v.x += bv.x; v.y += bv.y; v.z += bv.z; v.w += bv.w;
        }
        *(float4*)&Cb[(size_t)(r0 + i) * ldc + c0] = v;
    }
}

// ------------- K1: uv = h @ Wcomb  (M=4096, K=128, N=640), tf32-split mma -------------
// grid (64, 10), 128 threads (4 warps, 2x2 warp grid of 32x32 tiles)
__global__ __launch_bounds__(128) void k1_uv()
{
    __shared__ float Ah[64][36], Al[64][36];
    __shared__ float Bh[32][72], Bl[32][72];

    const int tid = threadIdx.x;
    const int warp = tid >> 5, lane = tid & 31;
    const int wm = warp >> 1, wn = warp & 1;
    const int g = lane >> 2, t4 = lane & 3;
    const int rowg = blockIdx.x * 64;
    const int colg = blockIdx.y * 64;

    float4 c[2][4];
    #pragma unroll
    for (int mi = 0; mi < 2; mi++)
        #pragma unroll
        for (int ni = 0; ni < 4; ni++) c[mi][ni] = make_float4(0.f,0.f,0.f,0.f);

    for (int kk = 0; kk < NE; kk += 32) {
        #pragma unroll
        for (int i = 0; i < 4; i++) {                  // A: 64x32 of h (hi/lo)
            int e = tid + i*128;
            int r = e >> 3, k = (e & 7) * 4;
            *(float4*)&Ah[r][k] = *(const float4*)&g_h_h[(size_t)(rowg + r)*NE + kk + k];
            *(float4*)&Al[r][k] = *(const float4*)&g_h_l[(size_t)(rowg + r)*NE + kk + k];
        }
        #pragma unroll
        for (int i = 0; i < 4; i++) {                  // B: 32x64 of Wcomb
            int e = tid + i*128;
            int k = e >> 4, n = (e & 15) * 4;
            *(float4*)&Bh[k][n] = *(const float4*)&g_Wc_h[(size_t)(kk + k)*UVW + colg + n];
            *(float4*)&Bl[k][n] = *(const float4*)&g_Wc_l[(size_t)(kk + k)*UVW + colg + n];
        }
        __syncthreads();
        #pragma unroll
        for (int k8 = 0; k8 < 32; k8 += 8) {
            unsigned ah[2][4], al[2][4], bh[4][2], bl[4][2];
            #pragma unroll
            for (int mi = 0; mi < 2; mi++) {
                int r = wm*32 + mi*16 + g;
                ah[mi][0] = __float_as_uint(Ah[r][k8 + t4]);
                ah[mi][1] = __float_as_uint(Ah[r + 8][k8 + t4]);
                ah[mi][2] = __float_as_uint(Ah[r][k8 + t4 + 4]);
                ah[mi][3] = __float_as_uint(Ah[r + 8][k8 + t4 + 4]);
                al[mi][0] = __float_as_uint(Al[r][k8 + t4]);
                al[mi][1] = __float_as_uint(Al[r + 8][k8 + t4]);
                al[mi][2] = __float_as_uint(Al[r][k8 + t4 + 4]);
                al[mi][3] = __float_as_uint(Al[r + 8][k8 + t4 + 4]);
            }
            #pragma unroll
            for (int ni = 0; ni < 4; ni++) {
                int n = wn*32 + ni*8 + g;
                bh[ni][0] = __float_as_uint(Bh[k8 + t4][n]);
                bh[ni][1] = __float_as_uint(Bh[k8 + t4 + 4][n]);
                bl[ni][0] = __float_as_uint(Bl[k8 + t4][n]);
                bl[ni][1] = __float_as_uint(Bl[k8 + t4 + 4][n]);
            }
            #pragma unroll
            for (int mi = 0; mi < 2; mi++)
                #pragma unroll
                for (int ni = 0; ni < 4; ni++) {
                    mma8(c[mi][ni], ah[mi], bh[ni]);
                    mma8(c[mi][ni], ah[mi], bl[ni]);
                    mma8(c[mi][ni], al[mi], bh[ni]);
                }
        }
        __syncthreads();
    }
    const bool isU = (colg < NE);
    #pragma unroll
    for (int mi = 0; mi < 2; mi++)
        #pragma unroll
        for (int ni = 0; ni < 4; ni++) {
            int row = rowg + wm*32 + mi*16 + g;
            int col = colg + wn*32 + ni*8 + t4*2;
            float4 v = c[mi][ni];
            if (isU) {
                float h0,l0,h1,l1,h2,l2,h3,l3;
                tfsplit(v.x,h0,l0); tfsplit(v.y,h1,l1);
                tfsplit(v.z,h2,l2); tfsplit(v.w,h3,l3);
                *(float2*)&g_u_h[(size_t)row*NE + col]     = make_float2(h0,h1);
                *(float2*)&g_u_l[(size_t)row*NE + col]     = make_float2(l0,l1);
                *(float2*)&g_u_h[(size_t)(row+8)*NE + col] = make_float2(h2,h3);
                *(float2*)&g_u_l[(size_t)(row+8)*NE + col] = make_float2(l2,l3);
            } else {
                *(float2*)&g_hw[(size_t)row*G4 + col - NE]     = make_float2(v.x,v.y);
                *(float2*)&g_hw[(size_t)(row+8)*G4 + col - NE] = make_float2(v.z,v.w);
            }
        }
}

// ------------- K2: Hu = An @ u  (batched: M=512, K=512, N=128 x 8) -------------
// grid (16, 2, 8), 128 threads (4 warps, 2x2 of 16x32 tiles)
__global__ __launch_bounds__(128) void k2_hu()
{
    __shared__ float Ah[32][36], Al[32][36];
    __shared__ float Bh[32][72], Bl[32][72];

    const int tid = threadIdx.x;
    const int warp = tid >> 5, lane = tid & 31;
    const int wm = warp >> 1, wn = warp & 1;
    const int g = lane >> 2, t4 = lane & 3;
    const int bz = blockIdx.z;
    const int rowg = blockIdx.x * 32;
    const int colg = blockIdx.y * 64;
    const size_t anbase = (size_t)bz * NNODE * NNODE;
    const int ubase = bz * NNODE;

    float4 c[4];
    #pragma unroll
    for (int ni = 0; ni < 4; ni++) c[ni] = make_float4(0.f,0.f,0.f,0.f);

    for (int kk = 0; kk < NNODE; kk += 32) {
        #pragma unroll
        for (int i = 0; i < 2; i++) {                  // A: 32x32 of An
            int e = tid + i*128;
            int r = e >> 3, k = (e & 7) * 4;
            *(float4*)&Ah[r][k] = *(const float4*)&g_An_h[anbase + (size_t)(rowg + r)*NNODE + kk + k];
            *(float4*)&Al[r][k] = *(const float4*)&g_An_l[anbase + (size_t)(rowg + r)*NNODE + kk + k];
        }
        #pragma unroll
        for (int i = 0; i < 4; i++) {                  // B: 32x64 of u
            int e = tid + i*128;
            int k = e >> 4, n = (e & 15) * 4;
            *(float4*)&Bh[k][n] = *(const float4*)&g_u_h[(size_t)(ubase + kk + k)*NE + colg + n];
            *(float4*)&Bl[k][n] = *(const float4*)&g_u_l[(size_t)(ubase + kk + k)*NE + colg + n];
        }
        __syncthreads();
        #pragma unroll
        for (int k8 = 0; k8 < 32; k8 += 8) {
            unsigned ah[4], al[4], bh[4][2], bl[4][2];
            int r = wm*16 + g;
            ah[0] = __float_as_uint(Ah[r][k8 + t4]);
            ah[1] = __float_as_uint(Ah[r + 8][k8 + t4]);
            ah[2] = __float_as_uint(Ah[r][k8 + t4 + 4]);
            ah[3] = __float_as_uint(Ah[r + 8][k8 + t4 + 4]);
            al[0] = __float_as_uint(Al[r][k8 + t4]);
            al[1] = __float_as_uint(Al[r + 8][k8 + t4]);
            al[2] = __float_as_uint(Al[r][k8 + t4 + 4]);
            al[3] = __float_as_uint(Al[r + 8][k8 + t4 + 4]);
            #pragma unroll
            for (int ni = 0; ni < 4; ni++) {
                int n = wn*32 + ni*8 + g;
                bh[ni][0] = __float_as_uint(Bh[k8 + t4][n]);
                bh[ni][1] = __float_as_uint(Bh[k8 + t4 + 4][n]);
                bl[ni][0] = __float_as_uint(Bl[k8 + t4][n]);
                bl[ni][1] = __float_as_uint(Bl[k8 + t4 + 4][n]);
            }
            #pragma unroll
            for (int ni = 0; ni < 4; ni++) {
                mma8(c[ni], ah, bh[ni]);
                mma8(c[ni], ah, bl[ni]);
                mma8(c[ni], al, bh[ni]);
            }
        }
        __syncthreads();
    }
    #pragma unroll
    for (int ni = 0; ni < 4; ni++) {
        int row = bz*NNODE + rowg + wm*16 + g;
        int col = colg + wn*32 + ni*8 + t4*2;
        float4 v = c[ni];
        float h0,l0,h1,l1,h2,l2,h3,l3;
        tfsplit(v.x,h0,l0); tfsplit(v.y,h1,l1);
        tfsplit(v.z,h2,l2); tfsplit(v.w,h3,l3);
        *(float2*)&g_Hu_h[(size_t)row*NE + col]     = make_float2(h0,h1);
        *(float2*)&g_Hu_l[(size_t)row*NE + col]     = make_float2(l0,l1);
        *(float2*)&g_Hu_h[(size_t)(row+8)*NE + col] = make_float2(h2,h3);
        *(float2*)&g_Hu_l[(size_t)(row+8)*NE + col] = make_float2(l2,l3);
    }
}

// ------------- K3: gates + LSTM + out-gemm -------------
// grid 128 (32 rows each), 256 threads (8 warps: 2(M) x 4(N))
__global__ __launch_bounds__(256) void k3_gates(
    float* __restrict__ out, const float* __restrict__ bout, int t)
{
    __shared__ float Ah[32][132], Al[32][132];
    __shared__ float Bh[8][136],  Bl[8][136];

    const int tid = threadIdx.x;
    const int warp = tid >> 5, lane = tid & 31;
    const int wm = warp >> 2, wn = warp & 3;
    const int g = lane >> 2, t4 = lane & 3;
    const int rg = blockIdx.x * 32;
    const int arow = wm*16 + g;

    #pragma unroll
    for (int i = 0; i < 4; i++) {                      // A: full 32x128 Hu tile
        int e = tid + i*256;
        int r = e >> 5, k = (e & 31) * 4;
        *(float4*)&Ah[r][k] = *(const float4*)&g_Hu_h[(size_t)(rg + r)*NE + k];
        *(float4*)&Al[r][k] = *(const float4*)&g_Hu_l[(size_t)(rg + r)*NE + k];
    }
    __syncthreads();

    float rb[4][4];
    const int order[4] = {0, 2, 1, 3};                 // i, g, f, o

    #pragma unroll
    for (int p = 0; p < 4; p++) {
        const int gb = order[p] << 7;
        float4 c[4];
        #pragma unroll
        for (int ni = 0; ni < 4; ni++) {               // init from esW + hw
            int col = gb + wn*32 + ni*8 + t4*2;
            size_t r0 = (size_t)(rg + arow)*G4 + col;
            size_t r1 = (size_t)(rg + arow + 8)*G4 + col;
            float2 e0 = *(const float2*)&g_esW[r0];
            float2 w0 = *(const float2*)&g_hw[r0];
            float2 e1 = *(const float2*)&g_esW[r1];
            float2 w1 = *(const float2*)&g_hw[r1];
            c[ni] = make_float4(e0.x + w0.x, e0.y + w0.y, e1.x + w1.x, e1.y + w1.y);
        }
        #pragma unroll 1
        for (int kk = 0; kk < NE; kk += 8) {
            {   // B chunk: 8x128 of WgH
                int k = tid >> 5, n = (lane) * 4;
                *(float4*)&Bh[k][n] = *(const float4*)&g_Wg_h[(size_t)(kk + k)*G4 + gb + n];
                *(float4*)&Bl[k][n] = *(const float4*)&g_Wg_l[(size_t)(kk + k)*G4 + gb + n];
            }
            __syncthreads();
            unsigned ah[4], al[4];
            ah[0] = __float_as_uint(Ah[arow][kk + t4]);
            ah[1] = __float_as_uint(Ah[arow + 8][kk + t4]);
            ah[2] = __float_as_uint(Ah[arow][kk + t4 + 4]);
            ah[3] = __float_as_uint(Ah[arow + 8][kk + t4 + 4]);
            al[0] = __float_as_uint(Al[arow][kk + t4]);
            al[1] = __float_as_uint(Al[arow + 8][kk + t4]);
            al[2] = __float_as_uint(Al[arow][kk + t4 + 4]);
            al[3] = __float_as_uint(Al[arow + 8][kk + t4 + 4]);
            #pragma unroll
            for (int ni = 0; ni < 4; ni++) {
                int n = wn*32 + ni*8 + g;
                unsigned bh2[2] = {__float_as_uint(Bh[t4][n]), __float_as_uint(Bh[t4+4][n])};
                unsigned bl2[2] = {__float_as_uint(Bl[t4][n]), __float_as_uint(Bl[t4+4][n])};
                mma8(c[ni], ah, bh2);
                mma8(c[ni], ah, bl2);
                mma8(c[ni], al, bh2);
            }
            __syncthreads();
        }
        if (p == 0) {
            #pragma unroll
            for (int ni = 0; ni < 4; ni++) {
                rb[ni][0] = sigm(c[ni].x); rb[ni][1] = sigm(c[ni].y);
                rb[ni][2] = sigm(c[ni].z); rb[ni][3] = sigm(c[ni].w);
            }
        } else if (p == 1) {
            #pragma unroll
            for (int ni = 0; ni < 4; ni++) {
                rb[ni][0] *= tanhf(c[ni].x); rb[ni][1] *= tanhf(c[ni].y);
                rb[ni][2] *= tanhf(c[ni].z); rb[ni][3] *= tanhf(c[ni].w);
            }
        } else if (p == 2) {
            #pragma unroll
            for (int ni = 0; ni < 4; ni++) {
                int col = wn*32 + ni*8 + t4*2;
                size_t cr0 = (size_t)(rg + arow)*NH + col;
                size_t cr1 = (size_t)(rg + arow + 8)*NH + col;
                float2 c0 = *(const float2*)&g_c[cr0];
                float2 c1 = *(const float2*)&g_c[cr1];
                float n0 = sigm(c[ni].x)*c0.x + rb[ni][0];
                float n1 = sigm(c[ni].y)*c0.y + rb[ni][1];
                float n2 = sigm(c[ni].z)*c1.x + rb[ni][2];
                float n3 = sigm(c[ni].w)*c1.y + rb[ni][3];
                *(float2*)&g_c[cr0] = make_float2(n0, n1);
                *(float2*)&g_c[cr1] = make_float2(n2, n3);
                rb[ni][0] = tanhf(n0); rb[ni][1] = tanhf(n1);
                rb[ni][2] = tanhf(n2); rb[ni][3] = tanhf(n3);
            }
        } else {
            #pragma unroll
            for (int ni = 0; ni < 4; ni++) {
                rb[ni][0] = sigm(c[ni].x)*rb[ni][0];
                rb[ni][1] = sigm(c[ni].y)*rb[ni][1];
                rb[ni][2] = sigm(c[ni].z)*rb[ni][2];
                rb[ni][3] = sigm(c[ni].w)*rb[ni][3];
            }
        }
    }

    // rb now holds h_t; write split to gmem + smem (reuse Ah/Al for h)
    __syncthreads();
    #pragma unroll
    for (int ni = 0; ni < 4; ni++) {
        int col = wn*32 + ni*8 + t4*2;
        float h0,l0,h1,l1,h2,l2,h3,l3;
        tfsplit(rb[ni][0], h0, l0); tfsplit(rb[ni][1], h1, l1);
        tfsplit(rb[ni][2], h2, l2); tfsplit(rb[ni][3], h3, l3);
        size_t gr0 = (size_t)(rg + arow)*NE + col;
        size_t gr1 = (size_t)(rg + arow + 8)*NE + col;
        *(float2*)&g_h_h[gr0] = make_float2(h0, h1);
        *(float2*)&g_h_l[gr0] = make_float2(l0, l1);
        *(float2*)&g_h_h[gr1] = make_float2(h2, h3);
        *(float2*)&g_h_l[gr1] = make_float2(l2, l3);
        Ah[arow][col] = h0;     Ah[arow][col+1] = h1;
        Ah[arow+8][col] = h2;   Ah[arow+8][col+1] = h3;
        Al[arow][col] = l0;     Al[arow][col+1] = l1;
        Al[arow+8][col] = l2;   Al[arow+8][col+1] = l3;
    }
    __syncthreads();

    // out-gemm: (32x64) = Xi + h @ Wout + bout ; warp tile 16x16 (ni 0..1)
    float4 oc[2];
    #pragma unroll
    for (int ni = 0; ni < 2; ni++) {
        int col = wn*16 + ni*8 + t4*2;
        float2 x0 = *(const float2*)&g_Xi[(size_t)(rg + arow)*NINP + col];
        float2 x1 = *(const float2*)&g_Xi[(size_t)(rg + arow + 8)*NINP + col];
        float2 b0 = *(const float2*)&bout[col];
        oc[ni] = make_float4(x0.x + b0.x, x0.y + b0.y, x1.x + b0.x, x1.y + b0.y);
    }
    #pragma unroll 1
    for (int kk = 0; kk < NE; kk += 8) {
        {   // Wo chunk: 8x64
            int k = tid >> 5, n = lane * 2;
            *(float2*)&Bh[k][n] = *(const float2*)&g_Wo_h[(size_t)(kk + k)*NINP + n];
            *(float2*)&Bl[k][n] = *(const float2*)&g_Wo_l[(size_t)(kk + k)*NINP + n];
        }
        __syncthreads();
        unsigned ah[4], al[4];
        ah[0] = __float_as_uint(Ah[arow][kk + t4]);
        ah[1] = __float_as_uint(Ah[arow + 8][kk + t4]);
        ah[2] = __float_as_uint(Ah[arow][kk + t4 + 4]);
        ah[3] = __float_as_uint(Ah[arow + 8][kk + t4 + 4]);
        al[0] = __float_as_uint(Al[arow][kk + t4]);
        al[1] = __float_as_uint(Al[arow + 8][kk + t4]);
        al[2] = __float_as_uint(Al[arow][kk + t4 + 4]);
        al[3] = __float_as_uint(Al[arow + 8][kk + t4 + 4]);
        #pragma unroll
        for (int ni = 0; ni < 2; ni++) {
            int n = wn*16 + ni*8 + g;
            unsigned bh2[2] = {__float_as_uint(Bh[t4][n]), __float_as_uint(Bh[t4+4][n])};
            unsigned bl2[2] = {__float_as_uint(Bl[t4][n]), __float_as_uint(Bl[t4+4][n])};
            mma8(oc[ni], ah, bh2);
            mma8(oc[ni], ah, bl2);
            mma8(oc[ni], al, bh2);
        }
        __syncthreads();
    }
    #pragma unroll
    for (int ni = 0; ni < 2; ni++) {
        int col = wn*16 + ni*8 + t4*2;
        size_t r0 = (size_t)(rg + arow);
        size_t r1 = (size_t)(rg + arow + 8);
        float2 v0 = make_float2(oc[ni].x, oc[ni].y);
        float2 v1 = make_float2(oc[ni].z, oc[ni].w);
        *(float2*)&g_Xi[r0*NINP + col] = v0;
        *(float2*)&g_Xi[r1*NINP + col] = v1;
        *(float2*)&out[r0*(TT*NINP) + (size_t)t*NINP + col] = v0;
        *(float2*)&out[r1*(TT*NINP) + (size_t)t*NINP + col] = v1;
    }
}

// ---------------- launch ----------------
extern "C" void kernel_launch(void* const* d_in, const int* in_sizes, int n_in,
                              void* d_out, int out_size)
{
    const float* X    = (const float*)d_in[0];
    const float* A    = (const float*)d_in[1];
    const float* Wse  = (const float*)d_in[2];
    const float* bse  = (const float*)d_in[3];
    const float* Wpe  = (const float*)d_in[4];
    const float* bpe  = (const float*)d_in[5];
    const float* Wii  = (const float*)d_in[6];
    const float* bii  = (const float*)d_in[7];
    const float* Whi  = (const float*)d_in[8];
    const float* bhi  = (const float*)d_in[9];
    const float* Wif  = (const float*)d_in[10];
    const float* bif_ = (const float*)d_in[11];
    const float* Whf  = (const float*)d_in[12];
    const float* bhf  = (const float*)d_in[13];
    const float* Wig  = (const float*)d_in[14];
    const float* big_ = (const float*)d_in[15];
    const float* Whg  = (const float*)d_in[16];
    const float* bhg  = (const float*)d_in[17];
    const float* Wio  = (const float*)d_in[18];
    const float* bio  = (const float*)d_in[19];
    const float* Who  = (const float*)d_in[20];
    const float* bho  = (const float*)d_in[21];
    const float* Wout = (const float*)d_in[22];
    const float* bout = (const float*)d_in[23];
    float* out = (float*)d_out;

    float *p_es, *p_esW, *p_Wtop, *p_cvec;
    cudaGetSymbolAddress((void**)&p_es,   g_es);
    cudaGetSymbolAddress((void**)&p_esW,  g_esW);
    cudaGetSymbolAddress((void**)&p_Wtop, g_Wtop);
    cudaGetSymbolAddress((void**)&p_cvec, g_cvec);

    int wtotal = NE*UVW + NE*G4 + G4 + NH*NINP;
    prep_weights<<<(wtotal + 255)/256, 256>>>(
        Wpe, bpe, Wii, bii, Whi, bhi, Wif, bif_, Whf, bhf,
        Wig, big_, Whg, bhg, Wio, bio, Who, bho, Wout);
    prep_dinv<<<RTOT, 128>>>(A);
    prep_An<<<(BB*NNODE*NNODE + 255)/256, 256>>>(A);
    prep_init<<<(RTOT*NH + 255)/256, 256>>>(X, out);
    prep_es<<<RTOT, 128>>>(X, Wse, bse);

    // esW = es @ Wtop + cvec   (M=4096, K=128, N=512), scalar one-time
    sgemm_t32<<<dim3(RTOT/32, G4/128), 256>>>(
        p_es, NE, p_Wtop, G4, p_esW, G4, NE, p_cvec);

    for (int t = 1; t < TT; ++t) {
        k1_uv<<<dim3(RTOT/64, UVW/64), 128>>>();
        k2_hu<<<dim3(NNODE/32, NE/64, BB), 128>>>();
        k3_gates<<<RTOT/32, 256>>>(out, bout, t);
    }
}

// round 5
// speedup vs baseline: 1.6358x; 1.4739x over previous
#include <cuda_runtime.h>
#include <math.h>

#define BB 8
#define NNODE 512
#define TT 64
#define NINP 64
#define NE 128
#define NH 128
#define RTOT 4096
#define G4 512
#define WTOT 704        /* 128 (u) + 512 (gates, interleaved) + 64 (out) */

// ---------------- scratch (allocation-free: __device__ globals) ----------------
__device__ float g_An[BB*NNODE*NNODE];     // normalized adjacency
__device__ float g_dinv[RTOT];
__device__ float g_c[RTOT*NH];
__device__ float g_h[RTOT*NH];
__device__ float g_u[RTOT*NE];             // u = h @ Wpe
__device__ float g_hw[RTOT*G4];            // h @ Wgates (interleaved cols)
__device__ float g_Hu4[4*RTOT*NH];         // split-K partials of An @ u
__device__ float g_es[RTOT*NE];
__device__ float g_esW[RTOT*G4];           // es@Wtop + cvec (interleaved)
__device__ float g_Xi[RTOT*NINP];
__device__ float g_Wc[NE*WTOT];            // [Wpe | gates-interleaved | Wout]
__device__ float g_Wg[NE*G4];              // bottom gate halves (interleaved)
__device__ float g_Wtop[NE*G4];            // top gate halves (interleaved)
__device__ float g_cvec[G4];               // b + bh + bpe@Wbot (interleaved)

__device__ __forceinline__ float sigm(float x) { return 1.f / (1.f + __expf(-x)); }

// ---------------- prep kernels ----------------
__global__ void prep_weights(
    const float* __restrict__ Wpe, const float* __restrict__ bpe,
    const float* __restrict__ Wii, const float* __restrict__ bii,
    const float* __restrict__ Whi, const float* __restrict__ bhi,
    const float* __restrict__ Wif, const float* __restrict__ bif_,
    const float* __restrict__ Whf, const float* __restrict__ bhf,
    const float* __restrict__ Wig, const float* __restrict__ big_,
    const float* __restrict__ Whg, const float* __restrict__ bhg,
    const float* __restrict__ Wio, const float* __restrict__ bio,
    const float* __restrict__ Who, const float* __restrict__ bho,
    const float* __restrict__ Wout)
{
    int idx = blockIdx.x * blockDim.x + threadIdx.x;
    const float* Wg[4]  = {Wii, Wif, Wig, Wio};
    const float* Whx[4] = {Whi, Whf, Whg, Who};
    const float* bg[4]  = {bii, bif_, big_, bio};
    const float* bhx[4] = {bhi, bhf, bhg, bho};

    if (idx < NE*WTOT) {                      // Wc = [Wpe | h-gates interleaved | Wout]
        int k = idx / WTOT, j = idx % WTOT;
        float v;
        if (j < NE) v = Wpe[k*NE + j];
        else if (j < 640) { int jj = j - NE; int jh = jj >> 2, g = jj & 3; v = Whx[g][k*NH + jh]; }
        else v = Wout[k*NINP + (j - 640)];
        g_Wc[idx] = v;
    }
    int i2 = idx - NE*WTOT;
    if (i2 >= 0 && i2 < NE*G4) {              // interleaved Wg (bottom) + Wtop (top)
        int k = i2 / G4, jj = i2 % G4; int jh = jj >> 2, g = jj & 3;
        g_Wg[i2]   = Wg[g][(NE + k)*NH + jh];
        g_Wtop[i2] = Wg[g][k*NH + jh];
    }
    int i3 = i2 - NE*G4;
    if (i3 >= 0 && i3 < G4) {                 // cvec = b + bh + bpe@Wbot (interleaved)
        int jh = i3 >> 2, g = i3 & 3;
        float s = bg[g][jh] + bhx[g][jh];
        for (int k = 0; k < NE; k++) s += bpe[k] * Wg[g][(NE + k)*NH + jh];
        g_cvec[i3] = s;
    }
}

__global__ void prep_dinv(const float* __restrict__ A)
{
    int row = blockIdx.x;
    const float* Ar = A + (size_t)row * NNODE;
    float s = 0.f;
    for (int j = threadIdx.x; j < NNODE; j += blockDim.x) s += Ar[j];
    __shared__ float red[4];
    for (int o = 16; o > 0; o >>= 1) s += __shfl_down_sync(0xffffffff, s, o);
    if ((threadIdx.x & 31) == 0) red[threadIdx.x >> 5] = s;
    __syncthreads();
    if (threadIdx.x == 0) {
        float d = red[0] + red[1] + red[2] + red[3];
        g_dinv[row] = d > 0.f ? rsqrtf(d) : 0.f;
    }
}

__global__ void prep_An(const float* __restrict__ A)
{
    int idx = blockIdx.x * blockDim.x + threadIdx.x;
    if (idx >= BB*NNODE*NNODE) return;
    int j  = idx & (NNODE - 1);
    int bi = idx >> 9;
    int b  = idx >> 18;
    g_An[idx] = A[idx] * g_dinv[bi] * g_dinv[(b << 9) + j];
}

__global__ void prep_init(const float* __restrict__ X, float* __restrict__ out)
{
    int idx = blockIdx.x * blockDim.x + threadIdx.x;
    if (idx < RTOT*G4) { g_hw[idx] = 0.f; g_Hu4[idx] = 0.f; }
    if (idx < RTOT*NH) { g_h[idx] = 0.f; g_c[idx] = 0.f; }
    if (idx < RTOT*NINP) {
        int r = idx >> 6, c = idx & 63;
        float v = X[(size_t)r * (TT*NINP) + c];
        g_Xi[idx] = v;
        out[(size_t)r * (TT*NINP) + c] = v;     // t = 0 slice
    }
}

__global__ void prep_es(const float* __restrict__ X,
                        const float* __restrict__ Wse, const float* __restrict__ bse)
{
    int r = blockIdx.x;
    __shared__ float xs[NINP];
    if (threadIdx.x < NINP) xs[threadIdx.x] = X[(size_t)r * (TT*NINP) + threadIdx.x];
    __syncthreads();
    int j = threadIdx.x;
    float s = bse[j];
    #pragma unroll 8
    for (int k = 0; k < NINP; k++) s += xs[k] * Wse[k*NE + j];
    g_es[r*NE + j] = s;
}

// ------------- one-time SGEMM: esW = es @ Wtop + cvec -------------
#define KC 16
__global__ __launch_bounds__(256) void sgemm_t32(
    const float* __restrict__ A, int lda,
    const float* __restrict__ B, int ldb,
    float* __restrict__ C, int ldc,
    int K, const float* __restrict__ bias)
{
    const float* Ab = A + (size_t)blockIdx.x * 32 * lda;
    const float* Bb = B + (size_t)blockIdx.y * 128;
    float*       Cb = C + (size_t)blockIdx.x * 32 * ldc + (size_t)blockIdx.y * 128;

    __shared__ float AsT[KC][36];
    __shared__ float Bss[KC][128];

    int tid = threadIdx.x;
    int tx = tid & 31, ty = tid >> 5;
    int r0 = ty * 4, c0 = tx * 4;

    float acc[4][4];
    #pragma unroll
    for (int i = 0; i < 4; i++)
        #pragma unroll
        for (int j = 0; j < 4; j++) acc[i][j] = 0.f;

    for (int kk = 0; kk < K; kk += KC) {
        #pragma unroll
        for (int e = 0; e < 2; e++) {
            int el = 2*tid + e;
            int ar = el >> 4, ak = el & 15;
            AsT[ak][ar] = Ab[(size_t)ar * lda + kk + ak];
        }
        #pragma unroll
        for (int e = 0; e < 8; e++) {
            int el = tid + e * 256;
            int bk = el >> 7, bc = el & 127;
            Bss[bk][bc] = Bb[(size_t)(kk + bk) * ldb + bc];
        }
        __syncthreads();
        #pragma unroll
        for (int k = 0; k < KC; k++) {
            float4 av = *(const float4*)&AsT[k][r0];
            float4 bv = *(const float4*)&Bss[k][c0];
            float a[4] = {av.x, av.y, av.z, av.w};
            float b[4] = {bv.x, bv.y, bv.z, bv.w};
            #pragma unroll
            for (int i = 0; i < 4; i++)
                #pragma unroll
                for (int j = 0; j < 4; j++) acc[i][j] += a[i] * b[j];
        }
        __syncthreads();
    }
    #pragma unroll
    for (int i = 0; i < 4; i++) {
        float4 v = make_float4(acc[i][0], acc[i][1], acc[i][2], acc[i][3]);
        if (bias) {
            const float4 bv = *(const float4*)&bias[blockIdx.y*128 + c0];
            v.x += bv.x; v.y += bv.y; v.z += bv.z; v.w += bv.w;
        }
        *(float4*)&Cb[(size_t)(r0 + i) * ldc + c0] = v;
    }
}

// ------------- K1: [u | hw | out_{t-1}] = h @ Wc  (M=4096, K=128, N=704) -------------
// tile 128x64, 128 threads, 8x8 micro. grid (32, ncolTiles)
__global__ __launch_bounds__(128) void k1(
    float* __restrict__ out, const float* __restrict__ bout, int t, int colbase)
{
    __shared__ float AsT[32][132];
    __shared__ float Bs[32][68];

    const int tid = threadIdx.x;
    const int ty = tid >> 3, tx = tid & 7;      // 16 row-groups x 8 col-groups
    const int rowg = blockIdx.x * 128;
    const int colg = colbase + blockIdx.y * 64;

    float acc[8][8];
    #pragma unroll
    for (int i = 0; i < 8; i++)
        #pragma unroll
        for (int j = 0; j < 8; j++) acc[i][j] = 0.f;

    for (int kk = 0; kk < NE; kk += 32) {
        #pragma unroll
        for (int k4 = 0; k4 < 8; k4++) {        // A: 128 rows x 32 k of h (transposed)
            float4 v = *(const float4*)&g_h[(size_t)(rowg + tid)*NH + kk + k4*4];
            AsT[k4*4+0][tid] = v.x; AsT[k4*4+1][tid] = v.y;
            AsT[k4*4+2][tid] = v.z; AsT[k4*4+3][tid] = v.w;
        }
        {                                        // B: 32 x 64 of Wc
            int bk = tid >> 2, c0 = (tid & 3) * 16;
            #pragma unroll
            for (int j = 0; j < 4; j++)
                *(float4*)&Bs[bk][c0 + j*4] =
                    *(const float4*)&g_Wc[(size_t)(kk + bk)*WTOT + colg + c0 + j*4];
        }
        __syncthreads();
        #pragma unroll
        for (int k = 0; k < 32; k++) {
            float a[8], b[8];
            *(float4*)&a[0] = *(const float4*)&AsT[k][ty*8];
            *(float4*)&a[4] = *(const float4*)&AsT[k][ty*8 + 4];
            *(float4*)&b[0] = *(const float4*)&Bs[k][tx*8];
            *(float4*)&b[4] = *(const float4*)&Bs[k][tx*8 + 4];
            #pragma unroll
            for (int i = 0; i < 8; i++)
                #pragma unroll
                for (int j = 0; j < 8; j++) acc[i][j] += a[i] * b[j];
        }
        __syncthreads();
    }

    if (colg < NE) {                             // -> g_u
        #pragma unroll
        for (int i = 0; i < 8; i++) {
            size_t row = rowg + ty*8 + i;
            *(float4*)&g_u[row*NE + colg + tx*8] =
                make_float4(acc[i][0], acc[i][1], acc[i][2], acc[i][3]);
            *(float4*)&g_u[row*NE + colg + tx*8 + 4] =
                make_float4(acc[i][4], acc[i][5], acc[i][6], acc[i][7]);
        }
    } else if (colg < 640) {                     // -> g_hw (interleaved gate cols)
        #pragma unroll
        for (int i = 0; i < 8; i++) {
            size_t row = rowg + ty*8 + i;
            int c = colg - NE + tx*8;
            *(float4*)&g_hw[row*G4 + c] =
                make_float4(acc[i][0], acc[i][1], acc[i][2], acc[i][3]);
            *(float4*)&g_hw[row*G4 + c + 4] =
                make_float4(acc[i][4], acc[i][5], acc[i][6], acc[i][7]);
        }
    } else {                                     // -> out_{t-1} = Xi + h@Wout + bout
        int o = colg - 640 + tx*8;
        float4 b0 = *(const float4*)&bout[o];
        float4 b1 = *(const float4*)&bout[o + 4];
        #pragma unroll
        for (int i = 0; i < 8; i++) {
            size_t row = rowg + ty*8 + i;
            float4 x0 = *(const float4*)&g_Xi[row*NINP + o];
            float4 x1 = *(const float4*)&g_Xi[row*NINP + o + 4];
            float4 v0 = make_float4(acc[i][0]+x0.x+b0.x, acc[i][1]+x0.y+b0.y,
                                    acc[i][2]+x0.z+b0.z, acc[i][3]+x0.w+b0.w);
            float4 v1 = make_float4(acc[i][4]+x1.x+b1.x, acc[i][5]+x1.y+b1.y,
                                    acc[i][6]+x1.z+b1.z, acc[i][7]+x1.w+b1.w);
            *(float4*)&g_Xi[row*NINP + o]     = v0;
            *(float4*)&g_Xi[row*NINP + o + 4] = v1;
            *(float4*)&out[row*(TT*NINP) + (size_t)(t-1)*NINP + o]     = v0;
            *(float4*)&out[row*(TT*NINP) + (size_t)(t-1)*NINP + o + 4] = v1;
        }
    }
}

// ------------- K2: Hu partial (split-K x4): An @ u -------------
// tile 64x128 per (batch, ksplit), 128 threads, 8x8 micro. grid (8, 1, 32)
__global__ __launch_bounds__(128) void k2()
{
    __shared__ float AsT[32][68];
    __shared__ float Bs[32][132];

    const int tid = threadIdx.x;
    const int ty = tid >> 4, tx = tid & 15;     // 8 x 16
    const int b  = blockIdx.z >> 2, ks = blockIdx.z & 3;
    const int rowg = blockIdx.x * 64;
    const int kbase = ks * 128;
    const size_t anb = (size_t)b * NNODE * NNODE;

    float acc[8][8];
    #pragma unroll
    for (int i = 0; i < 8; i++)
        #pragma unroll
        for (int j = 0; j < 8; j++) acc[i][j] = 0.f;

    for (int kk = 0; kk < 128; kk += 32) {
        {                                        // A: 64 rows x 32 k of An (transposed)
            int r = tid >> 1, kh = (tid & 1) * 16;
            #pragma unroll
            for (int j = 0; j < 4; j++) {
                float4 v = *(const float4*)&g_An[anb + (size_t)(rowg + r)*NNODE + kbase + kk + kh + j*4];
                AsT[kh + j*4 + 0][r] = v.x; AsT[kh + j*4 + 1][r] = v.y;
                AsT[kh + j*4 + 2][r] = v.z; AsT[kh + j*4 + 3][r] = v.w;
            }
        }
        {                                        // B: 32 k x 128 of u
            int bk = tid >> 2, c0 = (tid & 3) * 32;
            #pragma unroll
            for (int j = 0; j < 8; j++)
                *(float4*)&Bs[bk][c0 + j*4] =
                    *(const float4*)&g_u[(size_t)(b*NNODE + kbase + kk + bk)*NE + c0 + j*4];
        }
        __syncthreads();
        #pragma unroll
        for (int k = 0; k < 32; k++) {
            float a[8], bvv[8];
            *(float4*)&a[0] = *(const float4*)&AsT[k][ty*8];
            *(float4*)&a[4] = *(const float4*)&AsT[k][ty*8 + 4];
            *(float4*)&bvv[0] = *(const float4*)&Bs[k][tx*8];
            *(float4*)&bvv[4] = *(const float4*)&Bs[k][tx*8 + 4];
            #pragma unroll
            for (int i = 0; i < 8; i++)
                #pragma unroll
                for (int j = 0; j < 8; j++) acc[i][j] += a[i] * bvv[j];
        }
        __syncthreads();
    }
    #pragma unroll
    for (int i = 0; i < 8; i++) {
        size_t row = (size_t)b*NNODE + rowg + ty*8 + i;
        size_t base = (size_t)ks*(RTOT*NH) + row*NH + tx*8;
        *(float4*)&g_Hu4[base]     = make_float4(acc[i][0], acc[i][1], acc[i][2], acc[i][3]);
        *(float4*)&g_Hu4[base + 4] = make_float4(acc[i][4], acc[i][5], acc[i][6], acc[i][7]);
    }
}

// ------------- K3: gates = esW + hw + Hu@Wg ; LSTM state update -------------
// tile 32 rows x 256 gate-cols (64 hidden), 128 threads, 8x8 micro. grid (128, 2)
__global__ __launch_bounds__(128) void k3()
{
    __shared__ float AsT[128][36];               // Hu (merged), transposed [k][row]
    __shared__ float Bs[32][260];

    const int tid = threadIdx.x;
    const int ty = tid >> 5, tx = tid & 31;      // 4 x 32
    const int rg = blockIdx.x * 32;
    const int ch = blockIdx.y;                   // column half: hidden [ch*64, ch*64+64)

    {                                            // prologue: merge 4 Hu partials, transpose
        int row = tid & 31, kseg = (tid >> 5) * 32;
        #pragma unroll
        for (int k4 = 0; k4 < 8; k4++) {
            size_t idx = (size_t)(rg + row)*NH + kseg + k4*4;
            float4 s0 = *(const float4*)&g_Hu4[idx];
            float4 s1 = *(const float4*)&g_Hu4[(size_t)RTOT*NH + idx];
            float4 s2 = *(const float4*)&g_Hu4[2*(size_t)RTOT*NH + idx];
            float4 s3 = *(const float4*)&g_Hu4[3*(size_t)RTOT*NH + idx];
            AsT[kseg + k4*4 + 0][row] = s0.x + s1.x + s2.x + s3.x;
            AsT[kseg + k4*4 + 1][row] = s0.y + s1.y + s2.y + s3.y;
            AsT[kseg + k4*4 + 2][row] = s0.z + s1.z + s2.z + s3.z;
            AsT[kseg + k4*4 + 3][row] = s0.w + s1.w + s2.w + s3.w;
        }
    }
    __syncthreads();

    float acc[8][8];
    #pragma unroll
    for (int i = 0; i < 8; i++) {                // init from esW + hw
        size_t base = (size_t)(rg + ty*8 + i)*G4 + ch*256 + tx*8;
        float4 e0 = *(const float4*)&g_esW[base];
        float4 e1 = *(const float4*)&g_esW[base + 4];
        float4 w0 = *(const float4*)&g_hw[base];
        float4 w1 = *(const float4*)&g_hw[base + 4];
        acc[i][0] = e0.x + w0.x; acc[i][1] = e0.y + w0.y;
        acc[i][2] = e0.z + w0.z; acc[i][3] = e0.w + w0.w;
        acc[i][4] = e1.x + w1.x; acc[i][5] = e1.y + w1.y;
        acc[i][6] = e1.z + w1.z; acc[i][7] = e1.w + w1.w;
    }

    for (int kk = 0; kk < NE; kk += 32) {
        {                                        // B: 32 k x 256 of Wg
            int bk = tid >> 2, c0 = (tid & 3) * 64;
            #pragma unroll
            for (int j = 0; j < 16; j++)
                *(float4*)&Bs[bk][c0 + j*4] =
                    *(const float4*)&g_Wg[(size_t)(kk + bk)*G4 + ch*256 + c0 + j*4];
        }
        __syncthreads();
        #pragma unroll
        for (int k = 0; k < 32; k++) {
            float a[8], bvv[8];
            *(float4*)&a[0] = *(const float4*)&AsT[kk + k][ty*8];
            *(float4*)&a[4] = *(const float4*)&AsT[kk + k][ty*8 + 4];
            *(float4*)&bvv[0] = *(const float4*)&Bs[k][tx*8];
            *(float4*)&bvv[4] = *(const float4*)&Bs[k][tx*8 + 4];
            #pragma unroll
            for (int i = 0; i < 8; i++)
                #pragma unroll
                for (int j = 0; j < 8; j++) acc[i][j] += a[i] * bvv[j];
        }
        __syncthreads();
    }

    // elementwise LSTM: each thread has 8 rows x 2 hidden, gate quads (i,f,g,o)
    #pragma unroll
    for (int i = 0; i < 8; i++) {
        size_t row = rg + ty*8 + i;
        int hp = ch*64 + tx*2;
        float2 cold = *(const float2*)&g_c[row*NH + hp];
        float i0 = sigm(acc[i][0]), f0 = sigm(acc[i][1]);
        float gg0 = tanhf(acc[i][2]), o0 = sigm(acc[i][3]);
        float i1 = sigm(acc[i][4]), f1 = sigm(acc[i][5]);
        float gg1 = tanhf(acc[i][6]), o1 = sigm(acc[i][7]);
        float c0n = f0 * cold.x + i0 * gg0;
        float c1n = f1 * cold.y + i1 * gg1;
        *(float2*)&g_c[row*NH + hp] = make_float2(c0n, c1n);
        *(float2*)&g_h[row*NH + hp] = make_float2(o0 * tanhf(c0n), o1 * tanhf(c1n));
    }
}

// ---------------- launch ----------------
extern "C" void kernel_launch(void* const* d_in, const int* in_sizes, int n_in,
                              void* d_out, int out_size)
{
    const float* X    = (const float*)d_in[0];
    const float* A    = (const float*)d_in[1];
    const float* Wse  = (const float*)d_in[2];
    const float* bse  = (const float*)d_in[3];
    const float* Wpe  = (const float*)d_in[4];
    const float* bpe  = (const float*)d_in[5];
    const float* Wii  = (const float*)d_in[6];
    const float* bii  = (const float*)d_in[7];
    const float* Whi  = (const float*)d_in[8];
    const float* bhi  = (const float*)d_in[9];
    const float* Wif  = (const float*)d_in[10];
    const float* bif_ = (const float*)d_in[11];
    const float* Whf  = (const float*)d_in[12];
    const float* bhf  = (const float*)d_in[13];
    const float* Wig  = (const float*)d_in[14];
    const float* big_ = (const float*)d_in[15];
    const float* Whg  = (const float*)d_in[16];
    const float* bhg  = (const float*)d_in[17];
    const float* Wio  = (const float*)d_in[18];
    const float* bio  = (const float*)d_in[19];
    const float* Who  = (const float*)d_in[20];
    const float* bho  = (const float*)d_in[21];
    const float* Wout = (const float*)d_in[22];
    const float* bout = (const float*)d_in[23];
    float* out = (float*)d_out;

    float *p_es, *p_esW, *p_Wtop, *p_cvec;
    cudaGetSymbolAddress((void**)&p_es,   g_es);
    cudaGetSymbolAddress((void**)&p_esW,  g_esW);
    cudaGetSymbolAddress((void**)&p_Wtop, g_Wtop);
    cudaGetSymbolAddress((void**)&p_cvec, g_cvec);

    int wtotal = NE*WTOT + NE*G4 + G4;
    prep_weights<<<(wtotal + 255)/256, 256>>>(
        Wpe, bpe, Wii, bii, Whi, bhi, Wif, bif_, Whf, bhf,
        Wig, big_, Whg, bhg, Wio, bio, Who, bho, Wout);
    prep_dinv<<<RTOT, 128>>>(A);
    prep_An<<<(BB*NNODE*NNODE + 255)/256, 256>>>(A);
    prep_init<<<(RTOT*G4 + 255)/256, 256>>>(X, out);
    prep_es<<<RTOT, 128>>>(X, Wse, bse);

    // esW = es @ Wtop + cvec   (M=4096, K=128, N=512 interleaved)
    sgemm_t32<<<dim3(RTOT/32, G4/128), 256>>>(
        p_es, NE, p_Wtop, G4, p_esW, G4, NE, p_cvec);

    // t = 1: h0 = 0 -> u/hw/Hu are zero (pre-zeroed); only gates needed
    k3<<<dim3(RTOT/32, 2), 128>>>();

    for (int t = 2; t < TT; ++t) {
        k1<<<dim3(RTOT/128, WTOT/64), 128>>>(out, bout, t, 0);   // uv + out_{t-1}
        k2<<<dim3(NNODE/64, 1, 4*BB), 128>>>();                  // Hu partials
        k3<<<dim3(RTOT/32, 2), 128>>>();                         // gates + state
    }
    // tail: out_63 from h_63 (only the Wout column tile)
    k1<<<dim3(RTOT/128, 1), 128>>>(out, bout, TT, 640);
}